// round 5
// baseline (speedup 1.0000x reference)
#include <cuda_runtime.h>
#include <cstdint>

// Inputs (metadata order):
//   0: x        float32 [N=262144]
//   1: Param_W  float32 [1280]
//   2: Param_b  float32 [16]
//   3: w_rows   int32   [E=16777216]
//   4: w_cols   int32   [E]
//   5: w_params int32   [E]
//   6: b_params int32   [N]
// Output: float32 [N]

#define CLUSTER_SZ 8
#define TPB 1024
#define X_PER_CTA 32768            // floats per CTA slice (8 * 32768 = 262144 = N)
#define GRID_BLOCKS 144            // 18 clusters of 8, ~1 CTA/SM

__global__ void bias_init_kernel(const float* __restrict__ Pb,
                                 const int* __restrict__ b_params,
                                 float* __restrict__ out, int n) {
    int i = blockIdx.x * blockDim.x + threadIdx.x;
    if (i < n) {
        out[i] = __ldg(&Pb[b_params[i]]);
    }
}

// Gather x[col] from the cluster-distributed SMEM copy of x.
// Owner CTA rank = col >> 15, offset = col & 32767.
__device__ __forceinline__ float gather_x_dsmem(uint32_t xs_base, int col) {
    uint32_t rank = ((uint32_t)col) >> 15;
    uint32_t addr = xs_base + ((((uint32_t)col) & 32767u) << 2);
    uint32_t remote;
    asm("mapa.shared::cluster.u32 %0, %1, %2;" : "=r"(remote) : "r"(addr), "r"(rank));
    float v;
    asm volatile("ld.shared::cluster.f32 %0, [%1];" : "=f"(v) : "r"(remote));
    return v;
}

extern __shared__ float smem_x[];  // X_PER_CTA floats

__global__ void __cluster_dims__(CLUSTER_SZ, 1, 1) __launch_bounds__(TPB, 1)
edge_cluster_kernel(const float* __restrict__ x,
                    const float* __restrict__ Pw,
                    const int4* __restrict__ rows4,
                    const int4* __restrict__ cols4,
                    const int4* __restrict__ params4,
                    float* __restrict__ out,
                    int e4) {
    uint32_t rank;
    asm("mov.u32 %0, %%cluster_ctarank;" : "=r"(rank));

    // Stage this CTA's 128KB slice of x into SMEM (float4 loads, coalesced).
    {
        const float4* src = (const float4*)(x + (size_t)rank * X_PER_CTA);
        float4* dst = (float4*)smem_x;
        #pragma unroll 2
        for (int i = threadIdx.x; i < X_PER_CTA / 4; i += TPB)
            dst[i] = src[i];
    }

    // Cluster barrier: all slices staged + visible before any peer reads.
    asm volatile("barrier.cluster.arrive.aligned;" ::: "memory");
    asm volatile("barrier.cluster.wait.aligned;"   ::: "memory");

    uint32_t xs_base = (uint32_t)__cvta_generic_to_shared(smem_x);

    const int stride = GRID_BLOCKS * TPB;
    for (int i = blockIdx.x * TPB + threadIdx.x; i < e4; i += stride) {
        int4 r = rows4[i];
        int4 c = cols4[i];
        int4 p = params4[i];

        // DSMEM gathers for x (replaces 32B L2 sectors with 4B fabric reads).
        float x0 = gather_x_dsmem(xs_base, c.x);
        float x1 = gather_x_dsmem(xs_base, c.y);
        float x2 = gather_x_dsmem(xs_base, c.z);
        float x3 = gather_x_dsmem(xs_base, c.w);

        // Pw is 5KB — L1-resident via __ldg, keeps the SMEM port free
        // to serve peer DSMEM requests.
        float w0 = __ldg(&Pw[p.x]);
        float w1 = __ldg(&Pw[p.y]);
        float w2 = __ldg(&Pw[p.z]);
        float w3 = __ldg(&Pw[p.w]);

        // No-return atomicAdd -> REDG at LTS.
        atomicAdd(&out[r.x], w0 * x0);
        atomicAdd(&out[r.y], w1 * x1);
        atomicAdd(&out[r.z], w2 * x2);
        atomicAdd(&out[r.w], w3 * x3);
    }

    // No CTA may exit while peers might still read its SMEM slice.
    asm volatile("barrier.cluster.arrive.aligned;" ::: "memory");
    asm volatile("barrier.cluster.wait.aligned;"   ::: "memory");
}

extern "C" void kernel_launch(void* const* d_in, const int* in_sizes, int n_in,
                              void* d_out, int out_size) {
    const float* x        = (const float*)d_in[0];
    const float* Pw       = (const float*)d_in[1];
    const float* Pb       = (const float*)d_in[2];
    const int*   w_rows   = (const int*)d_in[3];
    const int*   w_cols   = (const int*)d_in[4];
    const int*   w_params = (const int*)d_in[5];
    const int*   b_params = (const int*)d_in[6];
    float* out = (float*)d_out;

    int N = out_size;            // 262144
    int E = in_sizes[3];         // 16777216

    // 1) out[i] = Param_b[b_params[i]]
    {
        int threads = 256;
        int blocks = (N + threads - 1) / threads;
        bias_init_kernel<<<blocks, threads>>>(Pb, b_params, out, N);
    }

    // 2) cluster-cached scatter-add over edges
    {
        static int smem_set = 0;
        size_t smem_bytes = (size_t)X_PER_CTA * sizeof(float);  // 128KB
        if (!smem_set) {
            cudaFuncSetAttribute(edge_cluster_kernel,
                                 cudaFuncAttributeMaxDynamicSharedMemorySize,
                                 (int)smem_bytes);
            smem_set = 1;
        }
        int e4 = E / 4;
        edge_cluster_kernel<<<GRID_BLOCKS, TPB, smem_bytes>>>(
            x, Pw,
            (const int4*)w_rows, (const int4*)w_cols, (const int4*)w_params,
            out, e4);
    }
}

// round 7
// speedup vs baseline: 2.8315x; 2.8315x over previous
#include <cuda_runtime.h>
#include <cstdint>

// Inputs (metadata order):
//   0: x        float32 [N=262144]
//   1: Param_W  float32 [1280]
//   2: Param_b  float32 [16]
//   3: w_rows   int32   [E=16777216]
//   4: w_cols   int32   [E]
//   5: w_params int32   [E]
//   6: b_params int32   [N]
// Output: float32 [N]

#define NPARAMS 1280

__global__ void bias_init_kernel(const float* __restrict__ Pb,
                                 const int* __restrict__ b_params,
                                 float* __restrict__ out, int n) {
    int i = blockIdx.x * blockDim.x + threadIdx.x;
    if (i < n) {
        out[i] = __ldg(&Pb[b_params[i]]);
    }
}

// x gather: keep x lines resident in L1 as long as possible.
__device__ __forceinline__ float ldg_evict_last(const float* p) {
    float v;
    asm volatile("ld.global.nc.L1::evict_last.f32 %0, [%1];"
                 : "=f"(v) : "l"(p));
    return v;
}

__global__ void __launch_bounds__(256) edge_scatter_kernel(
    const float* __restrict__ x,
    const float* __restrict__ Pw,
    const int4* __restrict__ rows4,
    const int4* __restrict__ cols4,
    const int4* __restrict__ params4,
    float* __restrict__ out,
    int e4) {
    // Stage Param_W (5KB) into SMEM: removes 16.7M global-load wavefronts
    // from L1tex (random 4B gathers over 40 lines were ~1 wavefront/lane).
    __shared__ float sPw[NPARAMS];
    #pragma unroll
    for (int k = threadIdx.x; k < NPARAMS; k += 256)
        sPw[k] = Pw[k];
    __syncthreads();

    int i = blockIdx.x * blockDim.x + threadIdx.x;
    if (i >= e4) return;

    // Streaming (evict-first) loads for the read-once index streams,
    // so they don't thrash x out of L1/L2.
    int4 r = __ldcs(&rows4[i]);
    int4 c = __ldcs(&cols4[i]);
    int4 p = __ldcs(&params4[i]);

    // Fire x gathers first for MLP; evict_last keeps x hot in L1.
    float x0 = ldg_evict_last(&x[c.x]);
    float x1 = ldg_evict_last(&x[c.y]);
    float x2 = ldg_evict_last(&x[c.z]);
    float x3 = ldg_evict_last(&x[c.w]);

    float w0 = sPw[p.x];
    float w1 = sPw[p.y];
    float w2 = sPw[p.z];
    float w3 = sPw[p.w];

    // No-return atomicAdd -> REDG at LTS.
    atomicAdd(&out[r.x], w0 * x0);
    atomicAdd(&out[r.y], w1 * x1);
    atomicAdd(&out[r.z], w2 * x2);
    atomicAdd(&out[r.w], w3 * x3);
}

extern "C" void kernel_launch(void* const* d_in, const int* in_sizes, int n_in,
                              void* d_out, int out_size) {
    const float* x        = (const float*)d_in[0];
    const float* Pw       = (const float*)d_in[1];
    const float* Pb       = (const float*)d_in[2];
    const int*   w_rows   = (const int*)d_in[3];
    const int*   w_cols   = (const int*)d_in[4];
    const int*   w_params = (const int*)d_in[5];
    const int*   b_params = (const int*)d_in[6];
    float* out = (float*)d_out;

    int N = out_size;            // 262144
    int E = in_sizes[3];         // 16777216

    // 1) out[i] = Param_b[b_params[i]]
    {
        int threads = 256;
        int blocks = (N + threads - 1) / threads;
        bias_init_kernel<<<blocks, threads>>>(Pb, b_params, out, N);
    }

    // 2) scatter-add edges
    {
        int e4 = E / 4;          // E divisible by 4
        int threads = 256;
        int blocks = (e4 + threads - 1) / threads;
        edge_scatter_kernel<<<blocks, threads>>>(
            x, Pw,
            (const int4*)w_rows, (const int4*)w_cols, (const int4*)w_params,
            out, e4);
    }
}